// round 15
// baseline (speedup 1.0000x reference)
#include <cuda_runtime.h>
#include <cstdint>

#define NN   50000
#define EE   600000
#define DIN  128
#define DHH  256
#define DOUT 128
#define BN_EPS 1e-5f

// ---------------- device scratch (static allocation only) ----------------
__device__ float g_bufA[(size_t)NN * DHH];   // activations
__device__ float g_bufB[(size_t)NN * DHH];   // aggregation output (z)
__device__ float g_bufC[(size_t)NN * DHH];   // MLP hidden
__device__ int   g_ptr[NN + 1];
__device__ int   g_ptr2[NN];
__device__ int   g_adj[EE];
__device__ int   g_src[EE];
__device__ int   g_dst[EE];
__device__ float g_sum[DHH];
__device__ float g_sumsq[DHH];
__device__ float g_scale[DHH];
__device__ float g_shift[DHH];
__device__ int   g_is64;

// ---------------- edge dtype detection + conversion ----------------
__global__ void set_flag_kernel() { g_is64 = 1; }

// If edge_index is int64, every odd 32-bit word (high half of a nonneg value)
// is 0. If int32, odd words are node ids in [0,50000) and are almost surely
// nonzero somewhere among 600k samples. Only reads within int32-sized buffer.
__global__ void detect64_kernel(const unsigned* __restrict__ w) {
    int i = blockIdx.x * blockDim.x + threadIdx.x;
    if (i >= EE) return;
    if (w[2 * i + 1] != 0u) g_is64 = 0;
}

__global__ void convert_edges_kernel(const void* __restrict__ ei) {
    int e = blockIdx.x * blockDim.x + threadIdx.x;
    if (e >= EE) return;
    if (g_is64) {
        const long long* p = (const long long*)ei;
        g_src[e] = (int)p[e];
        g_dst[e] = (int)p[(size_t)EE + e];
    } else {
        const int* p = (const int*)ei;
        g_src[e] = p[e];
        g_dst[e] = p[EE + e];
    }
}

// ---------------- CSR build ----------------
__global__ void zero_ptr_kernel() {
    int i = blockIdx.x * blockDim.x + threadIdx.x;
    if (i <= NN) g_ptr[i] = 0;
}

__global__ void hist_kernel() {
    int e = blockIdx.x * blockDim.x + threadIdx.x;
    if (e >= EE) return;
    atomicAdd(&g_ptr[g_dst[e]], 1);
}

// single-block exclusive scan over NN+1 entries (in place)
__global__ void scan_kernel() {
    __shared__ int s[1024];
    const int n = NN + 1;
    const int C = (n + 1023) / 1024;
    int t = threadIdx.x;
    int start = t * C;
    int sum = 0;
    for (int i = 0; i < C; i++) {
        int idx = start + i;
        if (idx < n) sum += g_ptr[idx];
    }
    s[t] = sum;
    __syncthreads();
    // Hillis-Steele inclusive scan
    for (int off = 1; off < 1024; off <<= 1) {
        int v = (t >= off) ? s[t - off] : 0;
        __syncthreads();
        s[t] += v;
        __syncthreads();
    }
    int run = (t > 0) ? s[t - 1] : 0;
    for (int i = 0; i < C; i++) {
        int idx = start + i;
        if (idx < n) {
            int tmp = g_ptr[idx];
            g_ptr[idx] = run;
            run += tmp;
        }
    }
}

__global__ void copy_ptr_kernel() {
    int i = blockIdx.x * blockDim.x + threadIdx.x;
    if (i < NN) g_ptr2[i] = g_ptr[i];
}

__global__ void fill_adj_kernel() {
    int e = blockIdx.x * blockDim.x + threadIdx.x;
    if (e >= EE) return;
    int pos = atomicAdd(&g_ptr2[g_dst[e]], 1);
    g_adj[pos] = g_src[e];
}

// ---------------- aggregation: z[n] = h[n] + sum_{src->n} h[src] ----------------
// one warp per node; NV4 float4 per lane (NV4*128 floats per row)
template <int NV4>
__global__ void agg_kernel(const float* __restrict__ h, float* __restrict__ out) {
    int gw   = (blockIdx.x * blockDim.x + threadIdx.x) >> 5;
    int lane = threadIdx.x & 31;
    if (gw >= NN) return;
    const int D = NV4 * 128;
    int beg = g_ptr[gw];
    int end = g_ptr[gw + 1];
    float4 acc[NV4];
    const float4* hrow = (const float4*)(h + (size_t)gw * D);
#pragma unroll
    for (int i = 0; i < NV4; i++) acc[i] = hrow[lane + i * 32];
    for (int j = beg; j < end; j++) {
        int srow = __ldg(&g_adj[j]);
        const float4* sr = (const float4*)(h + (size_t)srow * D);
#pragma unroll
        for (int i = 0; i < NV4; i++) {
            float4 v = sr[lane + i * 32];
            acc[i].x += v.x; acc[i].y += v.y; acc[i].z += v.z; acc[i].w += v.w;
        }
    }
    float4* orow = (float4*)(out + (size_t)gw * D);
#pragma unroll
    for (int i = 0; i < NV4; i++) orow[lane + i * 32] = acc[i];
}

// ---------------- fp32 SGEMM with fused bias: C = A(MxK) @ B(KxNcol) + bias ----------------
#define BM 128
#define BN 128
#define BK 16

__global__ void __launch_bounds__(256)
sgemm_bias_kernel(const float* __restrict__ A, const float* __restrict__ B,
                  const float* __restrict__ bias, float* __restrict__ C,
                  int M, int K, int Ncol) {
    __shared__ float As[BK][BM];
    __shared__ float Bs[BK][BN];

    int tid = threadIdx.x;
    int rowBase = blockIdx.y * BM;
    int colBase = blockIdx.x * BN;

    int ar  = tid >> 2;            // 0..63
    int ac  = (tid & 3) * 4;       // 0,4,8,12
    int bkr = tid >> 5;            // 0..7
    int bcc = (tid & 31) * 4;      // 0..124

    int tx = tid & 15;
    int ty = tid >> 4;

    float acc[8][8];
#pragma unroll
    for (int i = 0; i < 8; i++)
#pragma unroll
        for (int j = 0; j < 8; j++) acc[i][j] = 0.0f;

    for (int kt = 0; kt < K; kt += BK) {
        // load A tile (transposed into smem)
#pragma unroll
        for (int it = 0; it < 2; it++) {
            int r = ar + it * 64;
            int grow = rowBase + r;
            float4 v = make_float4(0.f, 0.f, 0.f, 0.f);
            if (grow < M) v = *(const float4*)&A[(size_t)grow * K + kt + ac];
            As[ac + 0][r] = v.x;
            As[ac + 1][r] = v.y;
            As[ac + 2][r] = v.z;
            As[ac + 3][r] = v.w;
        }
        // load B tile
#pragma unroll
        for (int it = 0; it < 2; it++) {
            int kr = bkr + it * 8;
            *(float4*)&Bs[kr][bcc] = *(const float4*)&B[(size_t)(kt + kr) * Ncol + colBase + bcc];
        }
        __syncthreads();

#pragma unroll
        for (int k = 0; k < BK; k++) {
            float ra[8], rb[8];
#pragma unroll
            for (int i = 0; i < 8; i++) ra[i] = As[k][ty * 8 + i];
#pragma unroll
            for (int j = 0; j < 8; j++) rb[j] = Bs[k][tx * 8 + j];
#pragma unroll
            for (int i = 0; i < 8; i++)
#pragma unroll
                for (int j = 0; j < 8; j++) acc[i][j] = fmaf(ra[i], rb[j], acc[i][j]);
        }
        __syncthreads();
    }

    float rbias[8];
#pragma unroll
    for (int j = 0; j < 8; j++) rbias[j] = bias[colBase + tx * 8 + j];

#pragma unroll
    for (int i = 0; i < 8; i++) {
        int grow = rowBase + ty * 8 + i;
        if (grow < M) {
            float* cp = &C[(size_t)grow * Ncol + colBase + tx * 8];
            float4 o0 = make_float4(acc[i][0] + rbias[0], acc[i][1] + rbias[1],
                                    acc[i][2] + rbias[2], acc[i][3] + rbias[3]);
            float4 o1 = make_float4(acc[i][4] + rbias[4], acc[i][5] + rbias[5],
                                    acc[i][6] + rbias[6], acc[i][7] + rbias[7]);
            *(float4*)cp       = o0;
            *(float4*)(cp + 4) = o1;
        }
    }
}

// ---------------- batchnorm (training-mode, biased var) ----------------
__global__ void zero_stats_kernel() {
    int c = threadIdx.x;
    g_sum[c] = 0.f;
    g_sumsq[c] = 0.f;
}

__global__ void colstats_kernel(const float* __restrict__ t, int M) {
    int col = threadIdx.x;  // 256 threads = one per column
    int rows = (M + gridDim.x - 1) / gridDim.x;
    int r0 = blockIdx.x * rows;
    int r1 = min(M, r0 + rows);
    float s = 0.f, s2 = 0.f;
    for (int r = r0; r < r1; r++) {
        float v = t[(size_t)r * DHH + col];
        s += v;
        s2 += v * v;
    }
    atomicAdd(&g_sum[col], s);
    atomicAdd(&g_sumsq[col], s2);
}

__global__ void bnparam_kernel(const float* __restrict__ gamma,
                               const float* __restrict__ beta, float invM) {
    int c = threadIdx.x;
    float mean = g_sum[c] * invM;
    float var = g_sumsq[c] * invM - mean * mean;
    float sc = gamma[c] * rsqrtf(var + BN_EPS);
    g_scale[c] = sc;
    g_shift[c] = beta[c] - mean * sc;
}

__global__ void bnrelu_kernel(float* __restrict__ t, int M) {
    size_t idx = (size_t)blockIdx.x * blockDim.x + threadIdx.x;  // one float4
    size_t total = (size_t)M * (DHH / 4);
    if (idx >= total) return;
    int c4 = (int)(idx & 63);
    float4 v = ((float4*)t)[idx];
    float4 sc = ((const float4*)g_scale)[c4];
    float4 sh = ((const float4*)g_shift)[c4];
    v.x = fmaxf(fmaf(v.x, sc.x, sh.x), 0.f);
    v.y = fmaxf(fmaf(v.y, sc.y, sh.y), 0.f);
    v.z = fmaxf(fmaf(v.z, sc.z, sh.z), 0.f);
    v.w = fmaxf(fmaf(v.w, sc.w, sh.w), 0.f);
    ((float4*)t)[idx] = v;
}

// ---------------- host orchestration ----------------
static inline void launch_gemm(const float* A, const float* B, const float* bias,
                               float* C, int M, int K, int Ncol) {
    dim3 grid((Ncol + BN - 1) / BN, (M + BM - 1) / BM);
    sgemm_bias_kernel<<<grid, 256>>>(A, B, bias, C, M, K, Ncol);
}

static inline void launch_bn(const float* t_unused, float* t, const float* gamma,
                             const float* beta) {
    zero_stats_kernel<<<1, DHH>>>();
    colstats_kernel<<<200, DHH>>>(t, NN);
    bnparam_kernel<<<1, DHH>>>(gamma, beta, 1.0f / (float)NN);
    size_t total = (size_t)NN * (DHH / 4);
    bnrelu_kernel<<<(unsigned)((total + 255) / 256), 256>>>(t, NN);
}

extern "C" void kernel_launch(void* const* d_in, const int* in_sizes, int n_in,
                              void* d_out, int out_size) {
    const float* x   = (const float*)d_in[0];
    const void*  ei  = d_in[1];
    const float* w1a = (const float*)d_in[2];
    const float* b1a = (const float*)d_in[3];
    const float* g1a = (const float*)d_in[4];
    const float* be1a= (const float*)d_in[5];
    const float* w1b = (const float*)d_in[6];
    const float* b1b = (const float*)d_in[7];
    const float* g1  = (const float*)d_in[8];
    const float* be1 = (const float*)d_in[9];
    const float* w2a = (const float*)d_in[10];
    const float* b2a = (const float*)d_in[11];
    const float* g2a = (const float*)d_in[12];
    const float* be2a= (const float*)d_in[13];
    const float* w2b = (const float*)d_in[14];
    const float* b2b = (const float*)d_in[15];
    const float* g2  = (const float*)d_in[16];
    const float* be2 = (const float*)d_in[17];
    const float* w3a = (const float*)d_in[18];
    const float* b3a = (const float*)d_in[19];
    const float* g3a = (const float*)d_in[20];
    const float* be3a= (const float*)d_in[21];
    const float* w3b = (const float*)d_in[22];
    const float* b3b = (const float*)d_in[23];
    float* out = (float*)d_out;

    float *bufA, *bufB, *bufC;
    cudaGetSymbolAddress((void**)&bufA, g_bufA);
    cudaGetSymbolAddress((void**)&bufB, g_bufB);
    cudaGetSymbolAddress((void**)&bufC, g_bufC);

    const int TB = 256;
    // ---- edge dtype detect + convert, CSR build (shared by all 3 layers) ----
    set_flag_kernel<<<1, 1>>>();
    detect64_kernel<<<(EE + TB - 1) / TB, TB>>>((const unsigned*)ei);
    convert_edges_kernel<<<(EE + TB - 1) / TB, TB>>>(ei);
    zero_ptr_kernel<<<(NN + 1 + TB - 1) / TB, TB>>>();
    hist_kernel<<<(EE + TB - 1) / TB, TB>>>();
    scan_kernel<<<1, 1024>>>();
    copy_ptr_kernel<<<(NN + TB - 1) / TB, TB>>>();
    fill_adj_kernel<<<(EE + TB - 1) / TB, TB>>>();

    const unsigned aggBlocks = (NN * 32 + TB - 1) / TB;

    // ---- layer 1 (DIN=128 -> 256 -> 256) ----
    agg_kernel<1><<<aggBlocks, TB>>>(x, bufB);
    launch_gemm(bufB, w1a, b1a, bufC, NN, DIN, DHH);
    launch_bn(bufC, bufC, g1a, be1a);
    launch_gemm(bufC, w1b, b1b, bufA, NN, DHH, DHH);
    launch_bn(bufA, bufA, g1, be1);   // outer bn1 + relu

    // ---- layer 2 (256 -> 256 -> 256) ----
    agg_kernel<2><<<aggBlocks, TB>>>(bufA, bufB);
    launch_gemm(bufB, w2a, b2a, bufC, NN, DHH, DHH);
    launch_bn(bufC, bufC, g2a, be2a);
    launch_gemm(bufC, w2b, b2b, bufA, NN, DHH, DHH);
    launch_bn(bufA, bufA, g2, be2);   // outer bn2 + relu

    // ---- layer 3 (256 -> 256 -> 128), no outer BN ----
    agg_kernel<2><<<aggBlocks, TB>>>(bufA, bufB);
    launch_gemm(bufB, w3a, b3a, bufC, NN, DHH, DHH);
    launch_bn(bufC, bufC, g3a, be3a);
    launch_gemm(bufC, w3b, b3b, out, NN, DHH, DOUT);

    (void)in_sizes; (void)n_in; (void)out_size;
}

// round 16
// speedup vs baseline: 1.0101x; 1.0101x over previous
#include <cuda_runtime.h>
#include <cstdint>

#define NN   50000
#define EE   600000
#define DIN  128
#define DHH  256
#define DOUT 128
#define BN_EPS 1e-5f

// ---------------- device scratch (static allocation only) ----------------
__device__ float g_bufA[(size_t)NN * DHH];   // activations
__device__ float g_bufB[(size_t)NN * DHH];   // aggregation output (z)
__device__ float g_bufC[(size_t)NN * DHH];   // MLP hidden
__device__ int   g_ptr[NN + 1];
__device__ int   g_ptr2[NN];
__device__ int   g_adj[EE];
__device__ int   g_src[EE];
__device__ int   g_dst[EE];
__device__ float g_sum[DHH];
__device__ float g_sumsq[DHH];
__device__ float g_scale[DHH];
__device__ float g_shift[DHH];
__device__ int   g_is64;

// ---------------- edge dtype detection + conversion ----------------
__global__ void set_flag_kernel() { g_is64 = 1; }

// If edge_index is int64, every odd 32-bit word (high half of a nonneg value)
// is 0. If int32, odd words are node ids in [0,50000) and are almost surely
// nonzero somewhere among 600k samples. Only reads within int32-sized buffer.
__global__ void detect64_kernel(const unsigned* __restrict__ w) {
    int i = blockIdx.x * blockDim.x + threadIdx.x;
    if (i >= EE) return;
    if (w[2 * i + 1] != 0u) g_is64 = 0;
}

__global__ void convert_edges_kernel(const void* __restrict__ ei) {
    int e = blockIdx.x * blockDim.x + threadIdx.x;
    if (e >= EE) return;
    if (g_is64) {
        const long long* p = (const long long*)ei;
        g_src[e] = (int)p[e];
        g_dst[e] = (int)p[(size_t)EE + e];
    } else {
        const int* p = (const int*)ei;
        g_src[e] = p[e];
        g_dst[e] = p[EE + e];
    }
}

// ---------------- CSR build ----------------
__global__ void zero_ptr_kernel() {
    int i = blockIdx.x * blockDim.x + threadIdx.x;
    if (i <= NN) g_ptr[i] = 0;
}

__global__ void hist_kernel() {
    int e = blockIdx.x * blockDim.x + threadIdx.x;
    if (e >= EE) return;
    atomicAdd(&g_ptr[g_dst[e]], 1);
}

// single-block exclusive scan over NN+1 entries (in place)
__global__ void scan_kernel() {
    __shared__ int s[1024];
    const int n = NN + 1;
    const int C = (n + 1023) / 1024;
    int t = threadIdx.x;
    int start = t * C;
    int sum = 0;
    for (int i = 0; i < C; i++) {
        int idx = start + i;
        if (idx < n) sum += g_ptr[idx];
    }
    s[t] = sum;
    __syncthreads();
    // Hillis-Steele inclusive scan
    for (int off = 1; off < 1024; off <<= 1) {
        int v = (t >= off) ? s[t - off] : 0;
        __syncthreads();
        s[t] += v;
        __syncthreads();
    }
    int run = (t > 0) ? s[t - 1] : 0;
    for (int i = 0; i < C; i++) {
        int idx = start + i;
        if (idx < n) {
            int tmp = g_ptr[idx];
            g_ptr[idx] = run;
            run += tmp;
        }
    }
}

__global__ void copy_ptr_kernel() {
    int i = blockIdx.x * blockDim.x + threadIdx.x;
    if (i < NN) g_ptr2[i] = g_ptr[i];
}

__global__ void fill_adj_kernel() {
    int e = blockIdx.x * blockDim.x + threadIdx.x;
    if (e >= EE) return;
    int pos = atomicAdd(&g_ptr2[g_dst[e]], 1);
    g_adj[pos] = g_src[e];
}

// ---------------- aggregation: z[n] = h[n] + sum_{src->n} h[src] ----------------
// one warp per node; NV4 float4 per lane (NV4*128 floats per row)
template <int NV4>
__global__ void agg_kernel(const float* __restrict__ h, float* __restrict__ out) {
    int gw   = (blockIdx.x * blockDim.x + threadIdx.x) >> 5;
    int lane = threadIdx.x & 31;
    if (gw >= NN) return;
    const int D = NV4 * 128;
    int beg = g_ptr[gw];
    int end = g_ptr[gw + 1];
    float4 acc[NV4];
    const float4* hrow = (const float4*)(h + (size_t)gw * D);
#pragma unroll
    for (int i = 0; i < NV4; i++) acc[i] = hrow[lane + i * 32];
    for (int j = beg; j < end; j++) {
        int srow = __ldg(&g_adj[j]);
        const float4* sr = (const float4*)(h + (size_t)srow * D);
#pragma unroll
        for (int i = 0; i < NV4; i++) {
            float4 v = sr[lane + i * 32];
            acc[i].x += v.x; acc[i].y += v.y; acc[i].z += v.z; acc[i].w += v.w;
        }
    }
    float4* orow = (float4*)(out + (size_t)gw * D);
#pragma unroll
    for (int i = 0; i < NV4; i++) orow[lane + i * 32] = acc[i];
}

// ---------------- fp32 SGEMM with fused bias: C = A(MxK) @ B(KxNcol) + bias ----------------
#define BM 128
#define BN 128
#define BK 16

__global__ void __launch_bounds__(256)
sgemm_bias_kernel(const float* __restrict__ A, const float* __restrict__ B,
                  const float* __restrict__ bias, float* __restrict__ C,
                  int M, int K, int Ncol) {
    __shared__ float As[BK][BM];
    __shared__ float Bs[BK][BN];

    int tid = threadIdx.x;
    int rowBase = blockIdx.y * BM;
    int colBase = blockIdx.x * BN;

    int ar  = tid >> 2;            // 0..63
    int ac  = (tid & 3) * 4;       // 0,4,8,12
    int bkr = tid >> 5;            // 0..7
    int bcc = (tid & 31) * 4;      // 0..124

    int tx = tid & 15;
    int ty = tid >> 4;

    float acc[8][8];
#pragma unroll
    for (int i = 0; i < 8; i++)
#pragma unroll
        for (int j = 0; j < 8; j++) acc[i][j] = 0.0f;

    for (int kt = 0; kt < K; kt += BK) {
        // load A tile (transposed into smem)
#pragma unroll
        for (int it = 0; it < 2; it++) {
            int r = ar + it * 64;
            int grow = rowBase + r;
            float4 v = make_float4(0.f, 0.f, 0.f, 0.f);
            if (grow < M) v = *(const float4*)&A[(size_t)grow * K + kt + ac];
            As[ac + 0][r] = v.x;
            As[ac + 1][r] = v.y;
            As[ac + 2][r] = v.z;
            As[ac + 3][r] = v.w;
        }
        // load B tile
#pragma unroll
        for (int it = 0; it < 2; it++) {
            int kr = bkr + it * 8;
            *(float4*)&Bs[kr][bcc] = *(const float4*)&B[(size_t)(kt + kr) * Ncol + colBase + bcc];
        }
        __syncthreads();

#pragma unroll
        for (int k = 0; k < BK; k++) {
            float ra[8], rb[8];
#pragma unroll
            for (int i = 0; i < 8; i++) ra[i] = As[k][ty * 8 + i];
#pragma unroll
            for (int j = 0; j < 8; j++) rb[j] = Bs[k][tx * 8 + j];
#pragma unroll
            for (int i = 0; i < 8; i++)
#pragma unroll
                for (int j = 0; j < 8; j++) acc[i][j] = fmaf(ra[i], rb[j], acc[i][j]);
        }
        __syncthreads();
    }

    float rbias[8];
#pragma unroll
    for (int j = 0; j < 8; j++) rbias[j] = bias[colBase + tx * 8 + j];

#pragma unroll
    for (int i = 0; i < 8; i++) {
        int grow = rowBase + ty * 8 + i;
        if (grow < M) {
            float* cp = &C[(size_t)grow * Ncol + colBase + tx * 8];
            float4 o0 = make_float4(acc[i][0] + rbias[0], acc[i][1] + rbias[1],
                                    acc[i][2] + rbias[2], acc[i][3] + rbias[3]);
            float4 o1 = make_float4(acc[i][4] + rbias[4], acc[i][5] + rbias[5],
                                    acc[i][6] + rbias[6], acc[i][7] + rbias[7]);
            *(float4*)cp       = o0;
            *(float4*)(cp + 4) = o1;
        }
    }
}

// ---------------- batchnorm (training-mode, biased var) ----------------
__global__ void zero_stats_kernel() {
    int c = threadIdx.x;
    g_sum[c] = 0.f;
    g_sumsq[c] = 0.f;
}

__global__ void colstats_kernel(const float* __restrict__ t, int M) {
    int col = threadIdx.x;  // 256 threads = one per column
    int rows = (M + gridDim.x - 1) / gridDim.x;
    int r0 = blockIdx.x * rows;
    int r1 = min(M, r0 + rows);
    float s = 0.f, s2 = 0.f;
    for (int r = r0; r < r1; r++) {
        float v = t[(size_t)r * DHH + col];
        s += v;
        s2 += v * v;
    }
    atomicAdd(&g_sum[col], s);
    atomicAdd(&g_sumsq[col], s2);
}

__global__ void bnparam_kernel(const float* __restrict__ gamma,
                               const float* __restrict__ beta, float invM) {
    int c = threadIdx.x;
    float mean = g_sum[c] * invM;
    float var = g_sumsq[c] * invM - mean * mean;
    float sc = gamma[c] * rsqrtf(var + BN_EPS);
    g_scale[c] = sc;
    g_shift[c] = beta[c] - mean * sc;
}

__global__ void bnrelu_kernel(float* __restrict__ t, int M) {
    size_t idx = (size_t)blockIdx.x * blockDim.x + threadIdx.x;  // one float4
    size_t total = (size_t)M * (DHH / 4);
    if (idx >= total) return;
    int c4 = (int)(idx & 63);
    float4 v = ((float4*)t)[idx];
    float4 sc = ((const float4*)g_scale)[c4];
    float4 sh = ((const float4*)g_shift)[c4];
    v.x = fmaxf(fmaf(v.x, sc.x, sh.x), 0.f);
    v.y = fmaxf(fmaf(v.y, sc.y, sh.y), 0.f);
    v.z = fmaxf(fmaf(v.z, sc.z, sh.z), 0.f);
    v.w = fmaxf(fmaf(v.w, sc.w, sh.w), 0.f);
    ((float4*)t)[idx] = v;
}

// ---------------- host orchestration ----------------
static inline void launch_gemm(const float* A, const float* B, const float* bias,
                               float* C, int M, int K, int Ncol) {
    dim3 grid((Ncol + BN - 1) / BN, (M + BM - 1) / BM);
    sgemm_bias_kernel<<<grid, 256>>>(A, B, bias, C, M, K, Ncol);
}

static inline void launch_bn(const float* t_unused, float* t, const float* gamma,
                             const float* beta) {
    zero_stats_kernel<<<1, DHH>>>();
    colstats_kernel<<<200, DHH>>>(t, NN);
    bnparam_kernel<<<1, DHH>>>(gamma, beta, 1.0f / (float)NN);
    size_t total = (size_t)NN * (DHH / 4);
    bnrelu_kernel<<<(unsigned)((total + 255) / 256), 256>>>(t, NN);
}

extern "C" void kernel_launch(void* const* d_in, const int* in_sizes, int n_in,
                              void* d_out, int out_size) {
    const float* x   = (const float*)d_in[0];
    const void*  ei  = d_in[1];
    const float* w1a = (const float*)d_in[2];
    const float* b1a = (const float*)d_in[3];
    const float* g1a = (const float*)d_in[4];
    const float* be1a= (const float*)d_in[5];
    const float* w1b = (const float*)d_in[6];
    const float* b1b = (const float*)d_in[7];
    const float* g1  = (const float*)d_in[8];
    const float* be1 = (const float*)d_in[9];
    const float* w2a = (const float*)d_in[10];
    const float* b2a = (const float*)d_in[11];
    const float* g2a = (const float*)d_in[12];
    const float* be2a= (const float*)d_in[13];
    const float* w2b = (const float*)d_in[14];
    const float* b2b = (const float*)d_in[15];
    const float* g2  = (const float*)d_in[16];
    const float* be2 = (const float*)d_in[17];
    const float* w3a = (const float*)d_in[18];
    const float* b3a = (const float*)d_in[19];
    const float* g3a = (const float*)d_in[20];
    const float* be3a= (const float*)d_in[21];
    const float* w3b = (const float*)d_in[22];
    const float* b3b = (const float*)d_in[23];
    float* out = (float*)d_out;

    float *bufA, *bufB, *bufC;
    cudaGetSymbolAddress((void**)&bufA, g_bufA);
    cudaGetSymbolAddress((void**)&bufB, g_bufB);
    cudaGetSymbolAddress((void**)&bufC, g_bufC);

    const int TB = 256;
    // ---- edge dtype detect + convert, CSR build (shared by all 3 layers) ----
    set_flag_kernel<<<1, 1>>>();
    detect64_kernel<<<(EE + TB - 1) / TB, TB>>>((const unsigned*)ei);
    convert_edges_kernel<<<(EE + TB - 1) / TB, TB>>>(ei);
    zero_ptr_kernel<<<(NN + 1 + TB - 1) / TB, TB>>>();
    hist_kernel<<<(EE + TB - 1) / TB, TB>>>();
    scan_kernel<<<1, 1024>>>();
    copy_ptr_kernel<<<(NN + TB - 1) / TB, TB>>>();
    fill_adj_kernel<<<(EE + TB - 1) / TB, TB>>>();

    const unsigned aggBlocks = (NN * 32 + TB - 1) / TB;

    // ---- layer 1 (DIN=128 -> 256 -> 256) ----
    agg_kernel<1><<<aggBlocks, TB>>>(x, bufB);
    launch_gemm(bufB, w1a, b1a, bufC, NN, DIN, DHH);
    launch_bn(bufC, bufC, g1a, be1a);
    launch_gemm(bufC, w1b, b1b, bufA, NN, DHH, DHH);
    launch_bn(bufA, bufA, g1, be1);   // outer bn1 + relu

    // ---- layer 2 (256 -> 256 -> 256) ----
    agg_kernel<2><<<aggBlocks, TB>>>(bufA, bufB);
    launch_gemm(bufB, w2a, b2a, bufC, NN, DHH, DHH);
    launch_bn(bufC, bufC, g2a, be2a);
    launch_gemm(bufC, w2b, b2b, bufA, NN, DHH, DHH);
    launch_bn(bufA, bufA, g2, be2);   // outer bn2 + relu

    // ---- layer 3 (256 -> 256 -> 128), no outer BN ----
    agg_kernel<2><<<aggBlocks, TB>>>(bufA, bufB);
    launch_gemm(bufB, w3a, b3a, bufC, NN, DHH, DHH);
    launch_bn(bufC, bufC, g3a, be3a);
    launch_gemm(bufC, w3b, b3b, out, NN, DHH, DOUT);

    (void)in_sizes; (void)n_in; (void)out_size;
}